// round 7
// baseline (speedup 1.0000x reference)
#include <cuda_runtime.h>
#include <cstdint>

#define HH 1024
#define WW 1024
#define HWs (HH*WW)
#define BIGV 1e9f
#define NEGB (-1e9f)
#define L2E 1.4426950408889634f

#define XW 71          // x window: [X0-3, X0+67]
#define PSTR 12        // floats per pixel slot: 8 ch + {f2,1.0} pair + 2 pad (48B, 16B aligned)
#define RSTR (XW*PSTR) // floats per row

typedef unsigned long long ull;

__device__ __forceinline__ ull pk(float a, float b) {
    ull r;
    asm("mov.b64 %0, {%1, %2};" : "=l"(r) : "f"(a), "f"(b));
    return r;
}
__device__ __forceinline__ void upk(ull v, float& a, float& b) {
    asm("mov.b64 {%0, %1}, %2;" : "=f"(a), "=f"(b) : "l"(v));
}
__device__ __forceinline__ ull fma2(ull a, ull b, ull c) {
    ull d;
    asm("fma.rn.f32x2 %0, %1, %2, %3;" : "=l"(d) : "l"(a), "l"(b), "l"(c));
    return d;
}
__device__ __forceinline__ float ex2(float x) {
    float y;
    asm("ex2.approx.f32 %0, %1;" : "=f"(y) : "f"(x));
    return y;
}
__device__ __forceinline__ float frcp(float x) {
    float y;
    asm("rcp.approx.f32 %0, %1;" : "=f"(y) : "f"(x));
    return y;
}

// Tile 64 wide x 8 tall. Block (64,4); thread (tx,ty) owns pixels
// (X0+tx, Y0+2ty) and (X0+tx, Y0+2ty+1) — vertically adjacent; each loaded
// neighbor value serves BOTH pixels. SMEM channel-interleaved, 48B pixel slot:
// words 0-7 = channels (2x LDS.128, conflict-free at stride 12),
// words 8-9 = pre-packed {f2, 1.0} (LDS.64 accumulate operand).
__global__ __launch_bounds__(256, 3)
void bilateral_kernel(const float* __restrict__ in, float* __restrict__ out)
{
    __shared__ float smf[14 * RSTR];   // 47712 B
    const int tx = threadIdx.x, ty = threadIdx.y;
    const int X0 = blockIdx.x * 64;
    const int Y0 = blockIdx.y * 8;
    const int b  = blockIdx.z;
    const float* __restrict__ inb = in + (size_t)b * 18 * HWs;

    // ---- fill channel-interleaved SMEM (+halo), sentinel for OOB ----
    const int tid = ty * 64 + tx;
    for (int i = tid; i < 14 * XW; i += 256) {
        int r = i / XW;
        int x = i - r * XW;
        int gy = Y0 - 3 + r;
        int gx = X0 - 3 + x;
        bool ok = ((unsigned)gx < WW) & ((unsigned)gy < HH);
        const float* g = inb + (size_t)gy * WW + gx;
        float4 u0, u1;
        u0.x = ok ? g[0 * HWs] : BIGV;
        u0.y = ok ? g[1 * HWs] : BIGV;
        u0.z = ok ? g[2 * HWs] : BIGV;
        u0.w = ok ? g[3 * HWs] : BIGV;
        u1.x = ok ? g[4 * HWs] : BIGV;
        u1.y = ok ? g[5 * HWs] : BIGV;
        u1.z = ok ? g[6 * HWs] : BIGV;
        u1.w = ok ? g[7 * HWs] : BIGV;
        float* d = &smf[r * RSTR + x * PSTR];
        *(float4*)d       = u0;
        *(float4*)(d + 4) = u1;
        *(ull*)(d + 8)    = pk(u0.z, 1.0f);     // {f2, 1.0}
    }
    __syncthreads();

    const int gx = X0 + tx;
    const int ya = Y0 + 2 * ty;      // pixel a; pixel b = ya + 1

    // ---- per-pixel precompute: rp' = -(p^2)*log2(e), u = -2 rp' f, v = sum rp' f^2 ----
    ull rppA[4], rppB[4], upA[4], upB[4];
    float va = 0.f, vb = 0.f;
    const float* __restrict__ pa = inb + 8 * HWs + (size_t)ya * WW + gx;
    const float* __restrict__ pbp = pa + WW;
    const float* __restrict__ ca = &smf[(2 * ty + 3) * RSTR + (tx + 3) * PSTR];
    const float* __restrict__ cb = ca + RSTR;
    #pragma unroll
    for (int k = 0; k < 4; k++) {
        float p0a = pa[(2*k) * HWs],  p1a = pa[(2*k+1) * HWs];
        float p0b = pbp[(2*k) * HWs], p1b = pbp[(2*k+1) * HWs];
        float r0a = -(p0a * p0a) * L2E, r1a = -(p1a * p1a) * L2E;
        float r0b = -(p0b * p0b) * L2E, r1b = -(p1b * p1b) * L2E;
        float f0a = ca[2*k], f1a = ca[2*k+1];
        float f0b = cb[2*k], f1b = cb[2*k+1];
        va = fmaf(r0a * f0a, f0a, va); va = fmaf(r1a * f1a, f1a, va);
        vb = fmaf(r0b * f0b, f0b, vb); vb = fmaf(r1b * f1b, f1b, vb);
        rppA[k] = pk(r0a, r1a);
        rppB[k] = pk(r0b, r1b);
        upA[k]  = pk(-2.f * r0a * f0a, -2.f * r1a * f1a);
        upB[k]  = pk(-2.f * r0b * f0b, -2.f * r1b * f1b);
    }
    float qa, qb;
    qa = pa[8 * HWs];  qb = pbp[8 * HWs];
    const float sxa = -(qa * qa) * L2E, sxb = -(qb * qb) * L2E;
    qa = pa[9 * HWs];  qb = pbp[9 * HWs];
    const float sya = -(qa * qa) * L2E, syb = -(qb * qb) * L2E;

    ull acc01a = 0ULL, acc01b = 0ULL;
    ull acc2wsa = 0ULL, acc2wsb = 0ULL;   // packed {acc2, wsum}

    // ---- main loop over 8 absolute rows (rolled), dx & channels unrolled ----
    for (int rr = 0; rr < 8; rr++) {
        int r = 2 * ty + rr;
        float da = (float)(rr - 3), db = (float)(rr - 4);
        float rba = (rr <= 6) ? fmaf(sya, da * da, va) : NEGB;  // mask invalid row, px a
        float rbb = (rr >= 1) ? fmaf(syb, db * db, vb) : NEGB;  // mask invalid row, px b
        // 4 packed bases per pixel for this row: {rb + {0,1,4,9}*sx, 0}
        ull pbA[4], pbB[4];
        pbA[0] = pk(rba, 0.f);
        pbA[1] = pk(fmaf(sxa, 1.f, rba), 0.f);
        pbA[2] = pk(fmaf(sxa, 4.f, rba), 0.f);
        pbA[3] = pk(fmaf(sxa, 9.f, rba), 0.f);
        pbB[0] = pk(rbb, 0.f);
        pbB[1] = pk(fmaf(sxb, 1.f, rbb), 0.f);
        pbB[2] = pk(fmaf(sxb, 4.f, rbb), 0.f);
        pbB[3] = pk(fmaf(sxb, 9.f, rbb), 0.f);
        const float* __restrict__ rowp = &smf[r * RSTR + tx * PSTR];
        #pragma unroll
        for (int dx = 0; dx < 7; dx++) {
            const int idx = (dx < 3) ? (3 - dx) : (dx - 3);   // compile-time per unrolled body

            const float* sp = rowp + dx * PSTR;
            ulonglong2 q0 = *(const ulonglong2*)sp;            // LDS.128: f01, f23
            ulonglong2 q1 = *(const ulonglong2*)(sp + 4);      // LDS.128: f45, f67
            ull pf21 = *(const ull*)(sp + 8);                  // LDS.64: {f2, 1.0}
            ull f01 = q0.x, f23 = q0.y, f45 = q1.x, f67 = q1.y;

            ull lwa = pbA[idx];
            ull lwb = pbB[idx];
            {
                ull s;
                s = fma2(rppA[0], f01, upA[0]); lwa = fma2(s, f01, lwa);
                s = fma2(rppB[0], f01, upB[0]); lwb = fma2(s, f01, lwb);
                s = fma2(rppA[1], f23, upA[1]); lwa = fma2(s, f23, lwa);
                s = fma2(rppB[1], f23, upB[1]); lwb = fma2(s, f23, lwb);
                s = fma2(rppA[2], f45, upA[2]); lwa = fma2(s, f45, lwa);
                s = fma2(rppB[2], f45, upB[2]); lwb = fma2(s, f45, lwb);
                s = fma2(rppA[3], f67, upA[3]); lwa = fma2(s, f67, lwa);
                s = fma2(rppB[3], f67, upB[3]); lwb = fma2(s, f67, lwb);
            }
            float ea, oa, eb, ob2;
            upk(lwa, ea, oa);
            upk(lwb, eb, ob2);
            float wa = ex2(ea + oa);
            float wb = ex2(eb + ob2);

            ull wwa = pk(wa, wa);
            ull wwb = pk(wb, wb);
            acc01a  = fma2(wwa, f01,  acc01a);
            acc2wsa = fma2(wwa, pf21, acc2wsa);
            acc01b  = fma2(wwb, f01,  acc01b);
            acc2wsb = fma2(wwb, pf21, acc2wsb);
        }
    }

    float acc2a, wsa, acc2b, wsb, a0, a1;
    upk(acc2wsa, acc2a, wsa);
    upk(acc2wsb, acc2b, wsb);
    const float ia = frcp(wsa), ib = frcp(wsb);
    float* __restrict__ oa = out + (size_t)b * 3 * HWs + (size_t)ya * WW + gx;
    float* __restrict__ ob = oa + WW;
    upk(acc01a, a0, a1);
    oa[0]   = a0 * ia;  oa[HWs] = a1 * ia;  oa[2 * HWs] = acc2a * ia;
    upk(acc01b, a0, a1);
    ob[0]   = a0 * ib;  ob[HWs] = a1 * ib;  ob[2 * HWs] = acc2b * ib;
}

extern "C" void kernel_launch(void* const* d_in, const int* in_sizes, int n_in,
                              void* d_out, int out_size) {
    const float* in = (const float*)d_in[0];
    float* out = (float*)d_out;
    dim3 grid(WW / 64, HH / 8, 2);
    dim3 block(64, 4);
    bilateral_kernel<<<grid, block>>>(in, out);
}